// round 7
// baseline (speedup 1.0000x reference)
#include <cuda_runtime.h>
#include <cuda_bf16.h>
#include <stdint.h>

#define QN 32
#define DN 4096
#define DIMN 384
#define N2 192
#define QD (QN*DN)
#define AW 100            // 96 words (384 int8) + 4 pad -> stride mod 32 = 4, conflict-free
#define BW1 196           // k1 bf16 W smem stride: 192 words + 4
#define S_H 0.35f

static __device__ __align__(16) float         g_A32[QN*DIMN];
static __device__ __align__(16) float         g_dense[QD];
static __device__ __align__(16) __nv_bfloat16 g_Bd[DN*DIMN];
static __device__ __align__(16) uint32_t      g_W2q[N2*96];       // int8 [n][k/4]
static __device__ __align__(16) __nv_bfloat16 g_W1dT[DIMN*DIMN];  // bf16 [n][k]
static __device__ uint32_t g_wmax_bits = 0u;

__device__ __forceinline__ void mma16816(float* c, const uint32_t* a, const uint32_t* b){
    asm volatile(
        "mma.sync.aligned.m16n8k16.row.col.f32.bf16.bf16.f32 "
        "{%0,%1,%2,%3}, {%4,%5,%6,%7}, {%8,%9}, {%0,%1,%2,%3};"
        : "+f"(c[0]), "+f"(c[1]), "+f"(c[2]), "+f"(c[3])
        : "r"(a[0]), "r"(a[1]), "r"(a[2]), "r"(a[3]), "r"(b[0]), "r"(b[1]));
}
__device__ __forceinline__ void mma16832s8(int* c, const uint32_t* a, const uint32_t* b){
    asm volatile(
        "mma.sync.aligned.m16n8k32.row.col.s32.s8.s8.s32 "
        "{%0,%1,%2,%3}, {%4,%5,%6,%7}, {%8,%9}, {%0,%1,%2,%3};"
        : "+r"(c[0]), "+r"(c[1]), "+r"(c[2]), "+r"(c[3])
        : "r"(a[0]), "r"(a[1]), "r"(a[2]), "r"(a[3]), "r"(b[0]), "r"(b[1]));
}
__device__ __forceinline__ uint32_t packbf(float x, float y){
    __nv_bfloat162 h = __floats2bfloat162_rn(x, y);
    return *(uint32_t*)&h;
}

// ---- prep: global max|W2| ------------------------------------------------
__global__ __launch_bounds__(256) void hr_prep_wmax(const float* __restrict__ W2)
{
    float m = 0.f;
    for (int i = blockIdx.x * 256 + threadIdx.x; i < N2 * DIMN; i += gridDim.x * 256)
        m = fmaxf(m, fabsf(W2[i]));
#pragma unroll
    for (int o = 16; o; o >>= 1) m = fmaxf(m, __shfl_xor_sync(0xffffffffu, m, o));
    if ((threadIdx.x & 31) == 0) atomicMax(&g_wmax_bits, __float_as_uint(m));
}

// ---- prep: quantize W2 -> int8, convert W1d^T -> bf16 --------------------
__global__ __launch_bounds__(256) void hr_prep_w(
    const float* __restrict__ W1, const float* __restrict__ W2)
{
    int i = blockIdx.x * 256 + threadIdx.x;
    if (i < N2 * 96) {
        int n = i / 96, w = i - n * 96, k = w * 4;
        float qwi = 127.f / __uint_as_float(g_wmax_bits);
        uint32_t p = 0;
#pragma unroll
        for (int j = 0; j < 4; j++) {
            int v = __float2int_rn(W2[(k + j) * N2 + n] * qwi);
            v = max(min(v, 127), -127);
            p |= ((uint32_t)(uint8_t)v) << (8 * j);
        }
        g_W2q[i] = p;
        return;
    }
    i -= N2 * 96;
    if (i < DIMN * DIMN) {
        int n = i / DIMN, k = i - n * DIMN;
        g_W1dT[i] = __float2bfloat16(W1[(DIMN + k) * DIMN + n]);
    }
}

// ---- prep: A32 = query @ W1q + b1 (fp32) ---------------------------------
__global__ __launch_bounds__(256) void hr_prep_a32(
    const float* __restrict__ qd, const float* __restrict__ W1, const float* __restrict__ b1)
{
    int idx = blockIdx.x * 256 + threadIdx.x;
    if (idx >= QN * DIMN) return;
    int qi = idx / DIMN, n = idx - qi * DIMN;
    float s = b1[n];
#pragma unroll 4
    for (int k = 0; k < DIMN; k++) s = fmaf(qd[qi * DIMN + k], W1[k * DIMN + n], s);
    g_A32[idx] = s;
}

// ---- prep: dense = query @ doc^T (fp32) ----------------------------------
__global__ __launch_bounds__(256) void hr_prep_dense(
    const float* __restrict__ qd, const float* __restrict__ doc)
{
    __shared__ float q_sh[QN * DIMN];
    int tid = threadIdx.x;
    for (int i = tid; i < QN * DIMN; i += 256) q_sh[i] = qd[i];
    __syncthreads();
    int w = tid >> 5, lane = tid & 31;
    int d = blockIdx.x * 8 + w;
    float dr[12];
#pragma unroll
    for (int i = 0; i < 12; i++) dr[i] = doc[(size_t)d * DIMN + lane + 32 * i];
    for (int qi = 0; qi < QN; qi++) {
        float s = 0.f;
#pragma unroll
        for (int i = 0; i < 12; i++) s = fmaf(dr[i], q_sh[qi * DIMN + lane + 32 * i], s);
#pragma unroll
        for (int o = 16; o; o >>= 1) s += __shfl_xor_sync(0xffffffffu, s, o);
        if (lane == 0) g_dense[qi * DN + d] = s;
    }
}

// ---- K1: Bd = doc @ W1d, bf16 HMMA, 256 CTAs (64x96 tiles) ---------------
__global__ __launch_bounds__(256, 2) void hr_k1(const float* __restrict__ doc)
{
    extern __shared__ uint32_t smw[];
    uint32_t* Wsm = smw;                 // [96][BW1]
    uint32_t* Asm = smw + 96 * BW1;      // [64][AW]
    const int tid = threadIdx.x, lane = tid & 31, wid = tid >> 5;
    const int wm = wid & 1, wn = wid >> 1;           // 2 x 4 warp grid
    const int d0 = (blockIdx.x >> 2) * 64, n0 = (blockIdx.x & 3) * 96;

    for (int i = tid; i < 96 * 192; i += 256) {
        int n = i / 192, w = i - n * 192;
        Wsm[n * BW1 + w] = ((const uint32_t*)g_W1dT)[(size_t)(n0 + n) * 192 + w];
    }
    float acc[2][3][4];
#pragma unroll
    for (int a = 0; a < 2; a++)
#pragma unroll
        for (int b = 0; b < 3; b++)
#pragma unroll
            for (int c = 0; c < 4; c++) acc[a][b][c] = 0.f;

    for (int ch = 0; ch < 2; ch++) {
        __syncthreads();
        for (int i = tid; i < 64 * 96; i += 256) {
            int r = i / 96, c = i - r * 96;
            float2 dv = *(const float2*)&doc[(size_t)(d0 + r) * DIMN + ch * 192 + 2 * c];
            Asm[r * AW + c] = packbf(dv.x, dv.y);
        }
        __syncthreads();
#pragma unroll
        for (int ks = 0; ks < 12; ks++) {
            uint32_t a[2][4], bf[3][2];
#pragma unroll
            for (int im = 0; im < 2; im++) {
                const uint32_t* p = Asm + (wm * 32 + im * 16 + (lane >> 2)) * AW + ks * 8 + (lane & 3);
                a[im][0] = p[0]; a[im][1] = p[8 * AW]; a[im][2] = p[4]; a[im][3] = p[8 * AW + 4];
            }
#pragma unroll
            for (int jn = 0; jn < 3; jn++) {
                const uint32_t* p = Wsm + (wn * 24 + jn * 8 + (lane >> 2)) * BW1 + ch * 96 + ks * 8 + (lane & 3);
                bf[jn][0] = p[0]; bf[jn][1] = p[4];
            }
#pragma unroll
            for (int im = 0; im < 2; im++)
#pragma unroll
                for (int jn = 0; jn < 3; jn++) mma16816(acc[im][jn], a[im], bf[jn]);
        }
    }
#pragma unroll
    for (int im = 0; im < 2; im++)
#pragma unroll
        for (int hf = 0; hf < 2; hf++) {
            int d = d0 + wm * 32 + im * 16 + hf * 8 + (lane >> 2);
#pragma unroll
            for (int jn = 0; jn < 3; jn++) {
                int n = n0 + wn * 24 + jn * 8 + (lane & 3) * 2;
                ((uint32_t*)g_Bd)[(size_t)d * 192 + (n >> 1)] =
                    packbf(acc[im][jn][hf * 2], acc[im][jn][hf * 2 + 1]);
            }
        }
}

// ---- K2: fused int8 h1 build + layer2 IMMA + epilogue, persistent --------
__global__ __launch_bounds__(256, 1) void hr_k2(
    const float* __restrict__ sparse, const float* __restrict__ W1,
    const float* __restrict__ b2, const float* __restrict__ W3,
    const float* __restrict__ b3, float* __restrict__ out, int out_size)
{
    extern __shared__ uint32_t smw[];
    uint32_t* Wsm = smw;                 // [192][AW] int8
    uint32_t* Asm = smw + N2 * AW;       // [128][AW] int8
    float* b2s = (float*)(Asm + 128 * AW);
    float* w3s = b2s + N2;
    float* a_s = w3s + N2;
    float* u_s = a_s + DIMN;
    float* v_s = u_s + DIMN;
    float* dns = v_s + DIMN;
    float* sps = dns + 128;
    float* zbuf = sps + 128;
    const int tid = threadIdx.x, lane = tid & 31, wid = tid >> 5;
    const int wm = wid & 1, wn = wid >> 1;
    const float sc  = (S_H / 127.f) * (__uint_as_float(g_wmax_bits) / 127.f);
    const float qhi = 127.f / S_H;

    for (int i = tid; i < N2 * 96; i += 256) {
        int n = i / 96, w = i - n * 96;
        Wsm[n * AW + w] = g_W2q[i];
    }
    for (int i = tid; i < N2; i += 256) { b2s[i] = b2[i]; w3s[i] = W3[i]; }
    for (int i = tid; i < DIMN; i += 256) {
        u_s[i] = W1[768 * DIMN + i];
        v_s[i] = W1[769 * DIMN + i];
    }

    for (int u = blockIdx.x; u < QN * 32; u += gridDim.x) {
        int q = u >> 5, dt = u & 31, d0 = dt << 7;
        __syncthreads();                                   // prev unit done with smem
        for (int i = tid; i < DIMN; i += 256) a_s[i] = g_A32[q * DIMN + i];
        if (tid < 128) {
            dns[tid] = g_dense[q * DN + d0 + tid];
            sps[tid] = sparse[q * DN + d0 + tid];
            zbuf[tid] = 0.f;
        }
        __syncthreads();
        // build full h1 tile int8 (128 x 384)
        for (int i = tid; i < 128 * 96; i += 256) {
            int r = i / 96, w = i - r * 96, k = w * 4;
            float4 av = *(const float4*)&a_s[k];
            float4 uv = *(const float4*)&u_s[k];
            float4 vv = *(const float4*)&v_s[k];
            float dsc = dns[r], ssc = sps[r];
            uint2 bw = *(const uint2*)((const uint32_t*)g_Bd + (size_t)(d0 + r) * 192 + w * 2);
            float2 b01 = __bfloat1622float2(*(__nv_bfloat162*)&bw.x);
            float2 b23 = __bfloat1622float2(*(__nv_bfloat162*)&bw.y);
            float x0 = fmaxf(av.x + b01.x + dsc * uv.x + ssc * vv.x, 0.f);
            float x1 = fmaxf(av.y + b01.y + dsc * uv.y + ssc * vv.y, 0.f);
            float x2 = fmaxf(av.z + b23.x + dsc * uv.z + ssc * vv.z, 0.f);
            float x3 = fmaxf(av.w + b23.y + dsc * uv.w + ssc * vv.w, 0.f);
            uint32_t v0 = (uint32_t)min(__float2int_rn(x0 * qhi), 127);
            uint32_t v1 = (uint32_t)min(__float2int_rn(x1 * qhi), 127);
            uint32_t v2 = (uint32_t)min(__float2int_rn(x2 * qhi), 127);
            uint32_t v3 = (uint32_t)min(__float2int_rn(x3 * qhi), 127);
            Asm[r * AW + w] = v0 | (v1 << 8) | (v2 << 16) | (v3 << 24);
        }
        __syncthreads();
        int acc[4][6][4];
#pragma unroll
        for (int a = 0; a < 4; a++)
#pragma unroll
            for (int b = 0; b < 6; b++)
#pragma unroll
                for (int c = 0; c < 4; c++) acc[a][b][c] = 0;
#pragma unroll
        for (int ks = 0; ks < 12; ks++) {
            int wk = ks * 8;
            uint32_t a[4][4], bfr[6][2];
#pragma unroll
            for (int im = 0; im < 4; im++) {
                const uint32_t* p = Asm + (wm * 64 + im * 16 + (lane >> 2)) * AW + wk + (lane & 3);
                a[im][0] = p[0]; a[im][1] = p[8 * AW]; a[im][2] = p[4]; a[im][3] = p[8 * AW + 4];
            }
#pragma unroll
            for (int jn = 0; jn < 6; jn++) {
                const uint32_t* p = Wsm + (wn * 48 + jn * 8 + (lane >> 2)) * AW + wk + (lane & 3);
                bfr[jn][0] = p[0]; bfr[jn][1] = p[4];
            }
#pragma unroll
            for (int im = 0; im < 4; im++)
#pragma unroll
                for (int jn = 0; jn < 6; jn++) mma16832s8(acc[im][jn], a[im], bfr[jn]);
        }
        // epilogue: z[m] = sum_n relu(sc*acc + b2) * W3
#pragma unroll
        for (int im = 0; im < 4; im++)
#pragma unroll
            for (int hf = 0; hf < 2; hf++) {
                int m = wm * 64 + im * 16 + hf * 8 + (lane >> 2);
                float val = 0.f;
#pragma unroll
                for (int jn = 0; jn < 6; jn++) {
                    int n = wn * 48 + jn * 8 + (lane & 3) * 2;
                    val += fmaxf((float)acc[im][jn][hf * 2]     * sc + b2s[n],     0.f) * w3s[n];
                    val += fmaxf((float)acc[im][jn][hf * 2 + 1] * sc + b2s[n + 1], 0.f) * w3s[n + 1];
                }
                val += __shfl_xor_sync(0xffffffffu, val, 1);
                val += __shfl_xor_sync(0xffffffffu, val, 2);
                if ((lane & 3) == 0) atomicAdd(&zbuf[m], val);
            }
        __syncthreads();
        if (tid < 128) {
            float z = zbuf[tid] + b3[0];
            float w = 1.f / (1.f + expf(-z));
            float dn = dns[tid], sp = sps[tid];
            float fin = w * dn + (1.f - w) * sp;
            int o = q * DN + d0 + tid;
            if (o < out_size)          out[o] = fin;
            if (QD + o < out_size)     out[QD + o] = dn;
            if (2 * QD + o < out_size) out[2 * QD + o] = sp;
        }
    }
}

extern "C" void kernel_launch(void* const* d_in, const int* in_sizes, int n_in,
                              void* d_out, int out_size)
{
    const float* qd     = (const float*)d_in[0];
    const float* doc    = (const float*)d_in[1];
    const float* sparse = (const float*)d_in[2];
    const float* W1     = (const float*)d_in[3];
    const float* b1     = (const float*)d_in[4];
    const float* W2     = (const float*)d_in[5];
    const float* b2     = (const float*)d_in[6];
    const float* W3     = (const float*)d_in[7];
    const float* b3     = (const float*)d_in[8];
    float* out = (float*)d_out;

    const int SMEM_K1 = (96 * BW1 + 64 * AW) * 4;                      // 100864
    const int SMEM_K2 = (N2 * AW + 128 * AW) * 4 + 1920 * 4;           // 135680
    cudaFuncSetAttribute(hr_k1, cudaFuncAttributeMaxDynamicSharedMemorySize, SMEM_K1);
    cudaFuncSetAttribute(hr_k2, cudaFuncAttributeMaxDynamicSharedMemorySize, SMEM_K2);

    hr_prep_wmax<<<72, 256>>>(W2);
    int wtot = N2 * 96 + DIMN * DIMN;
    hr_prep_w<<<(wtot + 255) / 256, 256>>>(W1, W2);
    hr_prep_a32<<<(QN * DIMN + 255) / 256, 256>>>(qd, W1, b1);
    hr_prep_dense<<<DN / 8, 256>>>(qd, doc);
    hr_k1<<<256, 256, SMEM_K1>>>(doc);
    hr_k2<<<148, 256, SMEM_K2>>>(sparse, W1, b2, W3, b3, out, out_size);
}

// round 8
// speedup vs baseline: 2.1258x; 2.1258x over previous
#include <cuda_runtime.h>
#include <cuda_bf16.h>
#include <stdint.h>

#define QN 32
#define DN 4096
#define DIMN 384
#define N2 192
#define QD (QN*DN)
#define AW 100            // h1/doc smem row stride in words (192 bf16 = 96 w + 4 pad)
#define BW1 196           // W smem row stride in words (384 bf16 = 192 w + 4 pad)

static __device__ __align__(16) float         g_A32[QN*DIMN];
static __device__ __align__(16) float         g_dense[QD];
static __device__ __align__(16) __nv_bfloat16 g_Bd[DN*DIMN];
static __device__ __align__(16) __nv_bfloat16 g_W2T[N2*DIMN];     // [n][k] bf16
static __device__ __align__(16) __nv_bfloat16 g_W1dT[DIMN*DIMN];  // [n][k] bf16

__device__ __forceinline__ void mma16816(float* c, const uint32_t* a, const uint32_t* b){
    asm volatile(
        "mma.sync.aligned.m16n8k16.row.col.f32.bf16.bf16.f32 "
        "{%0,%1,%2,%3}, {%4,%5,%6,%7}, {%8,%9}, {%0,%1,%2,%3};"
        : "+f"(c[0]), "+f"(c[1]), "+f"(c[2]), "+f"(c[3])
        : "r"(a[0]), "r"(a[1]), "r"(a[2]), "r"(a[3]), "r"(b[0]), "r"(b[1]));
}
__device__ __forceinline__ uint32_t packbf(float x, float y){
    __nv_bfloat162 h = __floats2bfloat162_rn(x, y);
    return *(uint32_t*)&h;
}

// ---- fused prep: [0,864) W transpose | [864,912) A32 | [912,1424) dense ---
#define PREP_WBLK 864
#define PREP_ABLK 48
#define PREP_DBLK 512
__global__ __launch_bounds__(256) void hr_prep(
    const float* __restrict__ qd, const float* __restrict__ doc,
    const float* __restrict__ W1, const float* __restrict__ W2,
    const float* __restrict__ b1)
{
    extern __shared__ float q_sh[];   // 48KB used only by dense role
    int blk = blockIdx.x, tid = threadIdx.x;

    if (blk < PREP_WBLK) {            // transpose/convert W2, W1d
        int i = blk * 256 + tid;
        if (i < N2 * DIMN) {
            int n = i / DIMN, k = i - n * DIMN;
            g_W2T[i] = __float2bfloat16(W2[k * N2 + n]);
        } else {
            i -= N2 * DIMN;
            int n = i / DIMN, k = i - n * DIMN;
            g_W1dT[i] = __float2bfloat16(W1[(DIMN + k) * DIMN + n]);
        }
        return;
    }
    if (blk < PREP_WBLK + PREP_ABLK) { // A32 = query @ W1q + b1
        int idx = (blk - PREP_WBLK) * 256 + tid;
        int qi = idx / DIMN, n = idx - qi * DIMN;
        float s = b1[n];
#pragma unroll 8
        for (int k = 0; k < DIMN; k++) s = fmaf(qd[qi * DIMN + k], W1[k * DIMN + n], s);
        g_A32[idx] = s;
        return;
    }
    {                                  // dense = query @ doc^T (fp32)
        int db = blk - PREP_WBLK - PREP_ABLK;
        for (int i = tid; i < QN * DIMN; i += 256) q_sh[i] = qd[i];
        __syncthreads();
        int w = tid >> 5, lane = tid & 31;
        int d = db * 8 + w;
        float dr[12];
#pragma unroll
        for (int i = 0; i < 12; i++) dr[i] = doc[(size_t)d * DIMN + lane + 32 * i];
        for (int qi = 0; qi < QN; qi++) {
            float s = 0.f;
#pragma unroll
            for (int i = 0; i < 12; i++) s = fmaf(dr[i], q_sh[qi * DIMN + lane + 32 * i], s);
#pragma unroll
            for (int o = 16; o; o >>= 1) s += __shfl_xor_sync(0xffffffffu, s, o);
            if (lane == 0) g_dense[qi * DN + d] = s;
        }
    }
}

// ---- K1: Bd = doc @ W1d, bf16 HMMA, 256 CTAs (64x96 tiles), occ 2 --------
__global__ __launch_bounds__(256, 2) void hr_k1(const float* __restrict__ doc)
{
    extern __shared__ uint32_t smw[];
    uint32_t* Wsm = smw;                 // [96][BW1]
    uint32_t* Asm = smw + 96 * BW1;      // [64][AW]
    const int tid = threadIdx.x, lane = tid & 31, wid = tid >> 5;
    const int wm = wid & 1, wn = wid >> 1;           // 2 x 4 warp grid
    const int d0 = (blockIdx.x >> 2) * 64, n0 = (blockIdx.x & 3) * 96;

    for (int i = tid; i < 96 * 192; i += 256) {
        int n = i / 192, w = i - n * 192;
        Wsm[n * BW1 + w] = ((const uint32_t*)g_W1dT)[(size_t)(n0 + n) * 192 + w];
    }
    float acc[2][3][4];
#pragma unroll
    for (int a = 0; a < 2; a++)
#pragma unroll
        for (int b = 0; b < 3; b++)
#pragma unroll
            for (int c = 0; c < 4; c++) acc[a][b][c] = 0.f;

    for (int ch = 0; ch < 2; ch++) {
        __syncthreads();
        for (int i = tid; i < 64 * 96; i += 256) {
            int r = i / 96, c = i - r * 96;
            float2 dv = *(const float2*)&doc[(size_t)(d0 + r) * DIMN + ch * 192 + 2 * c];
            Asm[r * AW + c] = packbf(dv.x, dv.y);
        }
        __syncthreads();
#pragma unroll
        for (int ks = 0; ks < 12; ks++) {
            uint32_t a[2][4], bf[3][2];
#pragma unroll
            for (int im = 0; im < 2; im++) {
                const uint32_t* p = Asm + (wm * 32 + im * 16 + (lane >> 2)) * AW + ks * 8 + (lane & 3);
                a[im][0] = p[0]; a[im][1] = p[8 * AW]; a[im][2] = p[4]; a[im][3] = p[8 * AW + 4];
            }
#pragma unroll
            for (int jn = 0; jn < 3; jn++) {
                const uint32_t* p = Wsm + (wn * 24 + jn * 8 + (lane >> 2)) * BW1 + ch * 96 + ks * 8 + (lane & 3);
                bf[jn][0] = p[0]; bf[jn][1] = p[4];
            }
#pragma unroll
            for (int im = 0; im < 2; im++)
#pragma unroll
                for (int jn = 0; jn < 3; jn++) mma16816(acc[im][jn], a[im], bf[jn]);
        }
    }
#pragma unroll
    for (int im = 0; im < 2; im++)
#pragma unroll
        for (int hf = 0; hf < 2; hf++) {
            int d = d0 + wm * 32 + im * 16 + hf * 8 + (lane >> 2);
#pragma unroll
            for (int jn = 0; jn < 3; jn++) {
                int n = n0 + wn * 24 + jn * 8 + (lane & 3) * 2;
                ((uint32_t*)g_Bd)[(size_t)d * 192 + (n >> 1)] =
                    packbf(acc[im][jn][hf * 2], acc[im][jn][hf * 2 + 1]);
            }
        }
}

// ---- K2: fused h1 + layer2 HMMA + epilogue, 512 threads, persistent ------
__global__ __launch_bounds__(512, 1) void hr_k2(
    const float* __restrict__ sparse, const float* __restrict__ W1,
    const float* __restrict__ b2, const float* __restrict__ W3,
    const float* __restrict__ b3, float* __restrict__ out, int out_size)
{
    extern __shared__ uint32_t smw[];
    uint32_t* Wsm = smw;                 // [192][BW1] bf16 W2^T
    uint32_t* Asm = smw + N2 * BW1;      // [128][AW] bf16 h1 chunk
    float* b2s = (float*)(Asm + 128 * AW);
    float* w3s = b2s + N2;
    float* a_s = w3s + N2;
    float* u_s = a_s + DIMN;
    float* v_s = u_s + DIMN;
    float* dns = v_s + DIMN;
    float* sps = dns + 128;
    float* zbuf = sps + 128;
    const int tid = threadIdx.x, lane = tid & 31, wid = tid >> 5;
    const int wm = wid & 3, wn = wid >> 2;   // 4 x 4 warp grid, tile 32m x 48n

    for (int i = tid; i < N2 * 48; i += 512) {       // W2^T via uint4
        int n = i / 48, w4 = i - n * 48;
        *(uint4*)&Wsm[n * BW1 + w4 * 4] = ((const uint4*)g_W2T)[(size_t)n * 48 + w4];
    }
    for (int i = tid; i < N2; i += 512) { b2s[i] = b2[i]; w3s[i] = W3[i]; }
    for (int i = tid; i < DIMN; i += 512) {
        u_s[i] = W1[768 * DIMN + i];
        v_s[i] = W1[769 * DIMN + i];
    }

    for (int u = blockIdx.x; u < QN * 32; u += gridDim.x) {
        int q = u >> 5, dt = u & 31, d0 = dt << 7;
        __syncthreads();                               // prev unit done with smem
        for (int i = tid; i < DIMN; i += 512) a_s[i] = g_A32[q * DIMN + i];
        if (tid < 128) {
            dns[tid] = g_dense[q * DN + d0 + tid];
            sps[tid] = sparse[q * DN + d0 + tid];
            zbuf[tid] = 0.f;
        }
        float acc[2][6][4];
#pragma unroll
        for (int a = 0; a < 2; a++)
#pragma unroll
            for (int b = 0; b < 6; b++)
#pragma unroll
                for (int c = 0; c < 4; c++) acc[a][b][c] = 0.f;

        for (int ch = 0; ch < 2; ch++) {
            __syncthreads();   // a_s visible (ch0) / prev mma done with Asm (ch1)
            // build h1 chunk: warp owns 8 rows, lanes cover 96 words
#pragma unroll 2
            for (int rr = 0; rr < 8; rr++) {
                int r = wid * 8 + rr;
                float dsc = dns[r], ssc = sps[r];
                const uint32_t* bdrow = (const uint32_t*)g_Bd + (size_t)(d0 + r) * 192 + ch * 96;
#pragma unroll
                for (int cc = 0; cc < 3; cc++) {
                    int c = lane + 32 * cc;
                    int k = ch * 192 + 2 * c;
                    uint32_t bdw = bdrow[c];
                    float2 bv = __bfloat1622float2(*(__nv_bfloat162*)&bdw);
                    float2 av = *(const float2*)&a_s[k];
                    float2 uv = *(const float2*)&u_s[k];
                    float2 vv = *(const float2*)&v_s[k];
                    float x0 = av.x + bv.x + dsc * uv.x + ssc * vv.x;
                    float x1 = av.y + bv.y + dsc * uv.y + ssc * vv.y;
                    Asm[r * AW + c] = packbf(fmaxf(x0, 0.f), fmaxf(x1, 0.f));
                }
            }
            __syncthreads();
#pragma unroll
            for (int ks = 0; ks < 12; ks++) {
                uint32_t a[2][4], bfr[6][2];
#pragma unroll
                for (int im = 0; im < 2; im++) {
                    const uint32_t* p = Asm + (wm * 32 + im * 16 + (lane >> 2)) * AW + ks * 8 + (lane & 3);
                    a[im][0] = p[0]; a[im][1] = p[8 * AW]; a[im][2] = p[4]; a[im][3] = p[8 * AW + 4];
                }
#pragma unroll
                for (int jn = 0; jn < 6; jn++) {
                    const uint32_t* p = Wsm + (wn * 48 + jn * 8 + (lane >> 2)) * BW1 + ch * 96 + ks * 8 + (lane & 3);
                    bfr[jn][0] = p[0]; bfr[jn][1] = p[4];
                }
#pragma unroll
                for (int im = 0; im < 2; im++)
#pragma unroll
                    for (int jn = 0; jn < 6; jn++) mma16816(acc[im][jn], a[im], bfr[jn]);
            }
        }
        // epilogue: z[m] = sum_n relu(D + b2) * W3
#pragma unroll
        for (int im = 0; im < 2; im++)
#pragma unroll
            for (int hf = 0; hf < 2; hf++) {
                int m = wm * 32 + im * 16 + hf * 8 + (lane >> 2);
                float val = 0.f;
#pragma unroll
                for (int jn = 0; jn < 6; jn++) {
                    int n = wn * 48 + jn * 8 + (lane & 3) * 2;
                    val += fmaxf(acc[im][jn][hf * 2]     + b2s[n],     0.f) * w3s[n];
                    val += fmaxf(acc[im][jn][hf * 2 + 1] + b2s[n + 1], 0.f) * w3s[n + 1];
                }
                val += __shfl_xor_sync(0xffffffffu, val, 1);
                val += __shfl_xor_sync(0xffffffffu, val, 2);
                if ((lane & 3) == 0) atomicAdd(&zbuf[m], val);
            }
        __syncthreads();
        if (tid < 128) {
            float z = zbuf[tid] + b3[0];
            float w = 1.f / (1.f + expf(-z));
            float dn = dns[tid], sp = sps[tid];
            float fin = w * dn + (1.f - w) * sp;
            int o = q * DN + d0 + tid;
            if (o < out_size)          out[o] = fin;
            if (QD + o < out_size)     out[QD + o] = dn;
            if (2 * QD + o < out_size) out[2 * QD + o] = sp;
        }
    }
}

extern "C" void kernel_launch(void* const* d_in, const int* in_sizes, int n_in,
                              void* d_out, int out_size)
{
    const float* qd     = (const float*)d_in[0];
    const float* doc    = (const float*)d_in[1];
    const float* sparse = (const float*)d_in[2];
    const float* W1     = (const float*)d_in[3];
    const float* b1     = (const float*)d_in[4];
    const float* W2     = (const float*)d_in[5];
    const float* b2     = (const float*)d_in[6];
    const float* W3     = (const float*)d_in[7];
    const float* b3     = (const float*)d_in[8];
    float* out = (float*)d_out;

    const int SMEM_PREP = QN * DIMN * 4;                          // 49152
    const int SMEM_K1 = (96 * BW1 + 64 * AW) * 4;                 // 100864
    const int SMEM_K2 = (N2 * BW1 + 128 * AW) * 4 + 1920 * 4;     // 209408
    cudaFuncSetAttribute(hr_prep, cudaFuncAttributeMaxDynamicSharedMemorySize, SMEM_PREP);
    cudaFuncSetAttribute(hr_k1, cudaFuncAttributeMaxDynamicSharedMemorySize, SMEM_K1);
    cudaFuncSetAttribute(hr_k2, cudaFuncAttributeMaxDynamicSharedMemorySize, SMEM_K2);

    hr_prep<<<PREP_WBLK + PREP_ABLK + PREP_DBLK, 256, SMEM_PREP>>>(qd, doc, W1, W2, b1);
    hr_k1<<<256, 256, SMEM_K1>>>(doc);
    hr_k2<<<148, 512, SMEM_K2>>>(sparse, W1, b2, W3, b3, out, out_size);
}